// round 12
// baseline (speedup 1.0000x reference)
#include <cuda_runtime.h>
#include <cuda_bf16.h>
#include <math.h>
#include <stdint.h>

#define BQ 16
#define CH 512
#define HH 56
#define WWD 56
#define NTOK 3136          // 56*56
#define NH 8
#define HD 64
#define AG 49
#define MROWS (BQ*NTOK)    // 50176
#define K2 1024            // packed K: [hi(512) | lo(512)]
#define NKIT 16            // 512 / 32 k-chunks
#define KS 4               // agent flash k-splits

// ---------------- scratch ----------------------------------------------------
__device__ float g_q[(size_t)MROWS * CH];
__device__ float g_k[(size_t)MROWS * CH];
__device__ float g_v[(size_t)MROWS * CH];
__device__ float g_pre[(size_t)MROWS * CH];
__device__ float g_agent[BQ * AG * CH];
__device__ float g_bias1[NH * AG * NTOK];          // [h][a][n]
__device__ float g_bias2[(size_t)NH * NTOK * AG];  // [h][n][a]
__device__ float g_agentv[BQ * NH * AG * HD];
__device__ float g_po[KS][BQ * NH][AG][HD];        // partial flash O
__device__ float g_pml[KS][BQ * NH][AG][2];        // partial flash m,l
__device__ __nv_bfloat16 g_abf[(size_t)MROWS * K2];
__device__ __nv_bfloat16 g_bbf[(size_t)3 * CH * K2];

// ---------------- helpers ----------------------------------------------------
__device__ __forceinline__ void split2(float v, __nv_bfloat16& hi, __nv_bfloat16& lo) {
    hi = __float2bfloat16(v);
    lo = __float2bfloat16(v - __bfloat162float(hi));
}
__device__ __forceinline__ uint32_t pack_bf2(__nv_bfloat16 a, __nv_bfloat16 b) {
    return ((uint32_t)__bfloat16_as_ushort(b) << 16) | (uint32_t)__bfloat16_as_ushort(a);
}
__device__ __forceinline__ uint32_t smem_u32(const void* p) {
    return (uint32_t)__cvta_generic_to_shared(p);
}
__device__ __forceinline__ void ldsm4(uint32_t& r0, uint32_t& r1, uint32_t& r2, uint32_t& r3, uint32_t addr) {
    asm volatile("ldmatrix.sync.aligned.m8n8.x4.shared.b16 {%0,%1,%2,%3}, [%4];"
                 : "=r"(r0), "=r"(r1), "=r"(r2), "=r"(r3) : "r"(addr));
}
__device__ __forceinline__ void ldsm4t(uint32_t& r0, uint32_t& r1, uint32_t& r2, uint32_t& r3, uint32_t addr) {
    asm volatile("ldmatrix.sync.aligned.m8n8.x4.trans.shared.b16 {%0,%1,%2,%3}, [%4];"
                 : "=r"(r0), "=r"(r1), "=r"(r2), "=r"(r3) : "r"(addr));
}
__device__ __forceinline__ void mma16816(float* c, const uint32_t* a, uint32_t b0, uint32_t b1) {
    asm volatile("mma.sync.aligned.m16n8k16.row.col.f32.bf16.bf16.f32 "
                 "{%0,%1,%2,%3}, {%4,%5,%6,%7}, {%8,%9}, {%0,%1,%2,%3};"
                 : "+f"(c[0]), "+f"(c[1]), "+f"(c[2]), "+f"(c[3])
                 : "r"(a[0]), "r"(a[1]), "r"(a[2]), "r"(a[3]), "r"(b0), "r"(b1));
}
__device__ __forceinline__ void cp16(uint32_t sp, const void* gp) {
    asm volatile("cp.async.cg.shared.global [%0], [%1], 16;\n" :: "r"(sp), "l"(gp));
}

// ---------------- pack kernels -----------------------------------------------
__global__ void pack_a(const float* __restrict__ src) {
    int row = blockIdx.x;
    int kp = threadIdx.x * 2;
    float2 v = *(const float2*)&src[(size_t)row * CH + kp];
    __nv_bfloat162 h2, l2;
    split2(v.x, h2.x, l2.x);
    split2(v.y, h2.y, l2.y);
    __nv_bfloat16* dst = g_abf + (size_t)row * K2;
    *(__nv_bfloat162*)&dst[kp]       = h2;
    *(__nv_bfloat162*)&dst[kp + 512] = l2;
}
__global__ void pack_a_dwc(const float* __restrict__ w, const float* __restrict__ dbias) {
    int row = blockIdx.x;           // b*3136 + n
    int c = threadIdx.x * 2;
    int n = row % NTOK, b = row / NTOK;
    int y = n / WWD, x = n % WWD;
    float a0 = dbias[c], a1 = dbias[c + 1];
#pragma unroll
    for (int ky = 0; ky < 3; ky++) {
        int yy = y + ky - 1;
        if (yy < 0 || yy >= HH) continue;
#pragma unroll
        for (int kx = 0; kx < 3; kx++) {
            int xx = x + kx - 1;
            if (xx < 0 || xx >= WWD) continue;
            float2 vv = *(const float2*)&g_v[((size_t)b * NTOK + yy * WWD + xx) * CH + c];
            int ki = ky * 3 + kx;
            a0 = fmaf(vv.x, w[c * 9 + ki], a0);
            a1 = fmaf(vv.y, w[(c + 1) * 9 + ki], a1);
        }
    }
    float2 p = *(const float2*)&g_pre[(size_t)row * CH + c];
    float v0 = p.x + a0, v1 = p.y + a1;
    __nv_bfloat162 h2, l2;
    split2(v0, h2.x, l2.x);
    split2(v1, h2.y, l2.y);
    __nv_bfloat16* dst = g_abf + (size_t)row * K2;
    *(__nv_bfloat162*)&dst[c]       = h2;
    *(__nv_bfloat162*)&dst[c + 512] = l2;
}
__global__ void pack_b(const float* __restrict__ w0, const float* __restrict__ w1, int qkv) {
    int row = blockIdx.x;
    int kp = threadIdx.x * 2;
    const float* src;
    if (qkv) src = (row < CH) ? (w0 + (size_t)row * CH) : (w1 + (size_t)(row - CH) * CH);
    else     src = w0 + (size_t)row * CH;
    float2 v = *(const float2*)&src[kp];
    __nv_bfloat162 h2, l2;
    split2(v.x, h2.x, l2.x);
    split2(v.y, h2.y, l2.y);
    __nv_bfloat16* dst = g_bbf + (size_t)row * K2;
    *(__nv_bfloat162*)&dst[kp]       = h2;
    *(__nv_bfloat162*)&dst[kp + 512] = l2;
}

// ---------------- split bf16 GEMM: C = Ah*Bh + Ah*Bl + Al*Bh ------------------
// 128x128 tile, 2-stage cp.async, 2 CTAs/SM.
#define OPS (128 * 40)
#define GS_DYN (2 * 4 * OPS * 2)
__global__ void __launch_bounds__(256, 2) gemm_split(int mode, const float* __restrict__ bias,
                                                     float* __restrict__ out) {
    extern __shared__ __nv_bfloat16 smg[];
    const int tid = threadIdx.x;
    const int lane = tid & 31;
    const int warp = tid >> 5;
    const int wm = (warp & 1) * 64;
    const int wn = (warp >> 1) * 32;
    const int m0 = blockIdx.y * 128;
    const int n0 = blockIdx.x * 128;
    const uint32_t sb = smem_u32(smg);

    float acc[4][4][4];
#pragma unroll
    for (int i = 0; i < 4; i++)
#pragma unroll
        for (int j = 0; j < 4; j++)
#pragma unroll
            for (int l = 0; l < 4; l++) acc[i][j][l] = 0.f;

#define ISSUE(st, ch)                                                                     \
    {                                                                                     \
        uint32_t bse = (uint32_t)(st) * (4 * OPS);                                        \
        _Pragma("unroll")                                                                 \
        for (int it = 0; it < 2; it++) {                                                  \
            int id = it * 256 + tid;                                                      \
            int row = id >> 2;                                                            \
            int c8 = (id & 3) * 8;                                                        \
            int k = (ch) * 32 + c8;                                                       \
            cp16(sb + (bse + row * 40 + c8) * 2,           g_abf + (size_t)(m0 + row) * K2 + k);        \
            cp16(sb + (bse + OPS + row * 40 + c8) * 2,     g_abf + (size_t)(m0 + row) * K2 + 512 + k);  \
            cp16(sb + (bse + 2 * OPS + row * 40 + c8) * 2, g_bbf + (size_t)(n0 + row) * K2 + k);        \
            cp16(sb + (bse + 3 * OPS + row * 40 + c8) * 2, g_bbf + (size_t)(n0 + row) * K2 + 512 + k);  \
        }                                                                                 \
        asm volatile("cp.async.commit_group;\n");                                         \
    }

    ISSUE(0, 0);
    for (int c = 0; c < NKIT; c++) {
        if (c + 1 < NKIT) {
            ISSUE((c + 1) & 1, c + 1);
            asm volatile("cp.async.wait_group 1;\n");
        } else {
            asm volatile("cp.async.wait_group 0;\n");
        }
        __syncthreads();
        uint32_t bse = (uint32_t)(c & 1) * (4 * OPS);
#pragma unroll
        for (int ks = 0; ks < 32; ks += 16) {
            uint32_t a_h[4][4], a_l[4][4];
#pragma unroll
            for (int fm = 0; fm < 4; fm++) {
                uint32_t ro = (uint32_t)((wm + fm * 16 + (lane & 15)) * 40 + ks + ((lane >> 4) << 3));
                ldsm4(a_h[fm][0], a_h[fm][1], a_h[fm][2], a_h[fm][3], sb + (bse + ro) * 2);
                ldsm4(a_l[fm][0], a_l[fm][1], a_l[fm][2], a_l[fm][3], sb + (bse + OPS + ro) * 2);
            }
#pragma unroll
            for (int fn = 0; fn < 2; fn++) {
                uint32_t ro = (uint32_t)((wn + fn * 16 + (lane & 7) + ((lane >> 4) << 3)) * 40
                                         + ks + (((lane >> 3) & 1) << 3));
                uint32_t bh[4], bl[4];
                ldsm4(bh[0], bh[1], bh[2], bh[3], sb + (bse + 2 * OPS + ro) * 2);
                ldsm4(bl[0], bl[1], bl[2], bl[3], sb + (bse + 3 * OPS + ro) * 2);
#pragma unroll
                for (int q = 0; q < 2; q++) {
                    int nc = fn * 2 + q;
                    uint32_t b0h = bh[q ? 2 : 0], b1h = bh[q ? 3 : 1];
                    uint32_t b0l = bl[q ? 2 : 0], b1l = bl[q ? 3 : 1];
#pragma unroll
                    for (int fm = 0; fm < 4; fm++) {
                        mma16816(acc[fm][nc], a_h[fm], b0h, b1h);
                        mma16816(acc[fm][nc], a_h[fm], b0l, b1l);
                        mma16816(acc[fm][nc], a_l[fm], b0h, b1h);
                    }
                }
            }
        }
        __syncthreads();
    }

    const int r0 = lane >> 2;
    const int cp = (lane & 3) * 2;
#pragma unroll
    for (int fm = 0; fm < 4; fm++) {
#pragma unroll
        for (int nc = 0; nc < 4; nc++) {
            int m = m0 + wm + fm * 16 + r0;
            int n = n0 + wn + nc * 8 + cp;
            if (mode == 0) {
                float* dst = (n < CH) ? g_q : ((n < 2 * CH) ? g_k : g_v);
                int nn = n & (CH - 1);
                *(float2*)&dst[(size_t)m * CH + nn] = make_float2(acc[fm][nc][0], acc[fm][nc][1]);
                *(float2*)&dst[(size_t)(m + 8) * CH + nn] = make_float2(acc[fm][nc][2], acc[fm][nc][3]);
            } else {
                float2 bb = *(const float2*)&bias[n];
                *(float2*)&out[(size_t)m * CH + n] =
                    make_float2(acc[fm][nc][0] + bb.x, acc[fm][nc][1] + bb.y);
                *(float2*)&out[(size_t)(m + 8) * CH + n] =
                    make_float2(acc[fm][nc][2] + bb.x, acc[fm][nc][3] + bb.y);
            }
        }
    }
#undef ISSUE
}

// ---------------- bias precompute --------------------------------------------
__device__ __forceinline__ float resize77(const float* __restrict__ img, int y, int x) {
    float sy = (y + 0.5f) * 0.125f - 0.5f;
    float sx = (x + 0.5f) * 0.125f - 0.5f;
    int y0 = (int)floorf(sy); float fy = sy - (float)y0;
    int x0 = (int)floorf(sx); float fx = sx - (float)x0;
    int y1 = y0 + 1, x1 = x0 + 1;
    float wy0 = 1.f - fy, wy1 = fy, wx0 = 1.f - fx, wx1 = fx;
    if (y0 < 0)  { y0 = 0; wy0 = 0.f; wy1 = 1.f; }
    if (y1 > 6)  { y1 = 6; wy0 = 1.f; wy1 = 0.f; }
    if (x0 < 0)  { x0 = 0; wx0 = 0.f; wx1 = 1.f; }
    if (x1 > 6)  { x1 = 6; wx0 = 1.f; wx1 = 0.f; }
    return wy0 * (wx0 * img[y0 * 7 + x0] + wx1 * img[y0 * 7 + x1]) +
           wy1 * (wx0 * img[y1 * 7 + x0] + wx1 * img[y1 * 7 + x1]);
}
__global__ void make_bias1(const float* __restrict__ an, const float* __restrict__ ahb,
                           const float* __restrict__ awb) {
    int h = blockIdx.y, a = blockIdx.x;
    const float* img = an + (h * AG + a) * 49;
    for (int n = threadIdx.x; n < NTOK; n += blockDim.x) {
        int y = n / WWD, x = n % WWD;
        g_bias1[(h * AG + a) * NTOK + n] =
            resize77(img, y, x) + ahb[(h * AG + a) * HH + y] + awb[(h * AG + a) * WWD + x];
    }
}
__global__ void make_bias2(const float* __restrict__ na, const float* __restrict__ hab,
                           const float* __restrict__ wab) {
    int h = blockIdx.y, n = blockIdx.x;
    int y = n / WWD, x = n % WWD;
    int a = threadIdx.x;
    if (a < AG) {
        g_bias2[((size_t)h * NTOK + n) * AG + a] =
            resize77(na + (h * AG + a) * 49, y, x) + hab[(h * HH + y) * AG + a] + wab[(h * WWD + x) * AG + a];
    }
}

// ---------------- agent pooling ----------------------------------------------
__global__ void agent_pool() {
    int a = blockIdx.x, b = blockIdx.y, c = threadIdx.x;
    int ph = a / 7, pw = a % 7;
    const float* base = g_q + (size_t)b * NTOK * CH;
    float s = 0.f;
#pragma unroll
    for (int ih = 0; ih < 8; ih++)
#pragma unroll
        for (int iw = 0; iw < 8; iw++)
            s += base[(size_t)((ph * 8 + ih) * WWD + pw * 8 + iw) * CH + c];
    g_agent[(b * AG + a) * CH + c] = s * (1.0f / 64.0f);
}

// ---------------- fused agent-side flash attention (k-split) ------------------
// Per (h, b, z): partial flash over n-tiles [z*25/4, (z+1)*25/4).
#define AF_DYN ((64 + 64 + 128 + 128 + 128 + 128) * 72 * 2)
__global__ void __launch_bounds__(128) agent_fused() {
    extern __shared__ __nv_bfloat16 smf[];
    __nv_bfloat16 (*sA0)[72] = (__nv_bfloat16(*)[72])smf;
    __nv_bfloat16 (*sA1)[72] = sA0 + 64;
    __nv_bfloat16 (*sK0)[72] = sA1 + 64;
    __nv_bfloat16 (*sK1)[72] = sK0 + 128;
    __nv_bfloat16 (*sV0)[72] = sK1 + 128;
    __nv_bfloat16 (*sV1)[72] = sV0 + 128;
    int h = blockIdx.x, b = blockIdx.y, z = blockIdx.z;
    int bh = b * NH + h;
    int tid = threadIdx.x, lane = tid & 31, warp = tid >> 5;
    int t0 = (z * 25) / KS, t1 = ((z + 1) * 25) / KS;

    {   // ah*scale split (rows >= 49 zero)
        int row = tid >> 1, c0 = (tid & 1) * 32;
        const float* src = g_agent + (size_t)(b * AG + row) * CH + h * HD + c0;
#pragma unroll
        for (int i = 0; i < 32; i += 2) {
            float2 v = (row < AG) ? *(const float2*)(src + i) : make_float2(0.f, 0.f);
            v.x *= 0.125f; v.y *= 0.125f;
            __nv_bfloat162 hi, lo;
            split2(v.x, hi.x, lo.x);
            split2(v.y, hi.y, lo.y);
            *(__nv_bfloat162*)&sA0[row][c0 + i] = hi;
            *(__nv_bfloat162*)&sA1[row][c0 + i] = lo;
        }
    }

    float m_run[2] = {-1e30f, -1e30f};
    float l_run[2] = {0.f, 0.f};
    float o[8][4];
#pragma unroll
    for (int j = 0; j < 8; j++)
#pragma unroll
        for (int e = 0; e < 4; e++) o[j][e] = 0.f;

    for (int t = t0; t < t1; t++) {
        int n0 = t * 128;
        __syncthreads();
        {   // load k,v tiles (128 rows x 64 cols), split hi/lo
            int n = n0 + tid;
            bool valid = (n < NTOK);
            const float* ksrc = g_k + ((size_t)b * NTOK + (valid ? n : 0)) * CH + h * HD;
            const float* vsrc = g_v + ((size_t)b * NTOK + (valid ? n : 0)) * CH + h * HD;
#pragma unroll
            for (int i = 0; i < 64; i += 2) {
                float2 kv = valid ? *(const float2*)(ksrc + i) : make_float2(0.f, 0.f);
                float2 vv = valid ? *(const float2*)(vsrc + i) : make_float2(0.f, 0.f);
                __nv_bfloat162 khi, klo, vhi, vlo;
                split2(kv.x, khi.x, klo.x); split2(kv.y, khi.y, klo.y);
                split2(vv.x, vhi.x, vlo.x); split2(vv.y, vhi.y, vlo.y);
                *(__nv_bfloat162*)&sK0[tid][i] = khi;
                *(__nv_bfloat162*)&sK1[tid][i] = klo;
                *(__nv_bfloat162*)&sV0[tid][i] = vhi;
                *(__nv_bfloat162*)&sV1[tid][i] = vlo;
            }
        }
        __syncthreads();

        // S = ah . k^T  (49x128), 3-term split
        float s[16][4];
#pragma unroll
        for (int j = 0; j < 16; j++)
#pragma unroll
            for (int e = 0; e < 4; e++) s[j][e] = 0.f;
#pragma unroll
        for (int kt = 0; kt < 4; kt++) {
            uint32_t a0[4], a1[4];
            uint32_t aro = smem_u32(&sA0[warp * 16 + (lane & 15)][kt * 16 + ((lane >> 4) << 3)]);
            uint32_t aro1 = smem_u32(&sA1[warp * 16 + (lane & 15)][kt * 16 + ((lane >> 4) << 3)]);
            ldsm4(a0[0], a0[1], a0[2], a0[3], aro);
            ldsm4(a1[0], a1[1], a1[2], a1[3], aro1);
#pragma unroll
            for (int p = 0; p < 8; p++) {
                uint32_t bro = (uint32_t)((p * 16 + (lane & 7) + ((lane >> 4) << 3)) * 72
                                          + kt * 16 + (((lane >> 3) & 1) << 3));
                uint32_t bh[4], bl[4];
                ldsm4(bh[0], bh[1], bh[2], bh[3], smem_u32(sK0) + bro * 2);
                ldsm4(bl[0], bl[1], bl[2], bl[3], smem_u32(sK1) + bro * 2);
                mma16816(s[p * 2],     a0, bh[0], bh[1]);
                mma16816(s[p * 2],     a0, bl[0], bl[1]);
                mma16816(s[p * 2],     a1, bh[0], bh[1]);
                mma16816(s[p * 2 + 1], a0, bh[2], bh[3]);
                mma16816(s[p * 2 + 1], a0, bl[2], bl[3]);
                mma16816(s[p * 2 + 1], a1, bh[2], bh[3]);
            }
        }

        // bias1 + mask + online softmax update
#pragma unroll
        for (int rh = 0; rh < 2; rh++) {
            int a = warp * 16 + (lane >> 2) + rh * 8;
            bool av = (a < AG);
            const float* b1p = g_bias1 + (size_t)(h * AG + (av ? a : 0)) * NTOK;
            float mx = m_run[rh];
#pragma unroll
            for (int j = 0; j < 16; j++) {
                int n = n0 + j * 8 + (lane & 3) * 2;
                bool nv = av && (n < NTOK);
                float2 bb = nv ? *(const float2*)(b1p + n) : make_float2(0.f, 0.f);
                float v0 = nv ? (s[j][rh * 2] + bb.x) : -1e30f;
                float v1 = nv ? (s[j][rh * 2 + 1] + bb.y) : -1e30f;
                s[j][rh * 2] = v0;
                s[j][rh * 2 + 1] = v1;
                mx = fmaxf(mx, fmaxf(v0, v1));
            }
            mx = fmaxf(mx, __shfl_xor_sync(0xffffffffu, mx, 1));
            mx = fmaxf(mx, __shfl_xor_sync(0xffffffffu, mx, 2));
            float scale = __expf(m_run[rh] - mx);
            float sum = 0.f;
#pragma unroll
            for (int j = 0; j < 16; j++) {
                float e0 = __expf(s[j][rh * 2] - mx);
                float e1 = __expf(s[j][rh * 2 + 1] - mx);
                s[j][rh * 2] = e0;
                s[j][rh * 2 + 1] = e1;
                sum += e0 + e1;
            }
            sum += __shfl_xor_sync(0xffffffffu, sum, 1);
            sum += __shfl_xor_sync(0xffffffffu, sum, 2);
            l_run[rh] = l_run[rh] * scale + sum;
            m_run[rh] = mx;
#pragma unroll
            for (int j = 0; j < 8; j++) {
                o[j][rh * 2] *= scale;
                o[j][rh * 2 + 1] *= scale;
            }
        }

        // O += P @ V
#pragma unroll
        for (int kt = 0; kt < 8; kt++) {
            uint32_t ah4[4], al4[4];
#pragma unroll
            for (int q = 0; q < 2; q++) {
                int j = kt * 2 + q;
#pragma unroll
                for (int rh = 0; rh < 2; rh++) {
                    __nv_bfloat16 h0, l0, h1, l1;
                    split2(s[j][rh * 2], h0, l0);
                    split2(s[j][rh * 2 + 1], h1, l1);
                    ah4[q * 2 + rh] = pack_bf2(h0, h1);
                    al4[q * 2 + rh] = pack_bf2(l0, l1);
                }
            }
#pragma unroll
            for (int dp = 0; dp < 4; dp++) {
                uint32_t bro = (uint32_t)((kt * 16 + (lane & 15)) * 72 + dp * 16 + ((lane >> 4) << 3));
                uint32_t vh[4], vl[4];
                ldsm4t(vh[0], vh[1], vh[2], vh[3], smem_u32(sV0) + bro * 2);
                ldsm4t(vl[0], vl[1], vl[2], vl[3], smem_u32(sV1) + bro * 2);
                mma16816(o[dp * 2],     ah4, vh[0], vh[1]);
                mma16816(o[dp * 2],     ah4, vl[0], vl[1]);
                mma16816(o[dp * 2],     al4, vh[0], vh[1]);
                mma16816(o[dp * 2 + 1], ah4, vh[2], vh[3]);
                mma16816(o[dp * 2 + 1], ah4, vl[2], vl[3]);
                mma16816(o[dp * 2 + 1], al4, vh[2], vh[3]);
            }
        }
    }

    // store partial (o, m, l)
#pragma unroll
    for (int rh = 0; rh < 2; rh++) {
        int a = warp * 16 + (lane >> 2) + rh * 8;
        if (a < AG) {
            float* dst = g_po[z][bh][a];
#pragma unroll
            for (int j = 0; j < 8; j++) {
                int d = j * 8 + (lane & 3) * 2;
                *(float2*)(dst + d) = make_float2(o[j][rh * 2], o[j][rh * 2 + 1]);
            }
            if ((lane & 3) == 0) {
                g_pml[z][bh][a][0] = m_run[rh];
                g_pml[z][bh][a][1] = l_run[rh];
            }
        }
    }
}

// combine partial flash results across KS splits
__global__ void agent_combine() {
    int bh = blockIdx.x;
    int d = threadIdx.x;   // 64
    for (int a = 0; a < AG; a++) {
        float m = -1e30f;
#pragma unroll
        for (int z = 0; z < KS; z++) m = fmaxf(m, g_pml[z][bh][a][0]);
        float l = 0.f, o = 0.f;
#pragma unroll
        for (int z = 0; z < KS; z++) {
            float w = __expf(g_pml[z][bh][a][0] - m);
            l = fmaf(g_pml[z][bh][a][1], w, l);
            o = fmaf(g_po[z][bh][a][d], w, o);
        }
        g_agentv[((size_t)bh * AG + a) * HD + d] = o / l;
    }
}

// ---------------- q-side fused flash (mma.sync) -------------------------------
__global__ void __launch_bounds__(128) qside_mma() {
    __shared__ __nv_bfloat16 sQ[128][72];
    __shared__ __nv_bfloat16 sB0[64][72];
    __shared__ __nv_bfloat16 sB1[64][72];
    int b = blockIdx.z, h = blockIdx.y, m0 = blockIdx.x * 128;
    int tid = threadIdx.x, lane = tid & 31, warp = tid >> 5;

    {
        int row = tid >> 1, c0 = (tid & 1) * 32;
        const float* src = g_agent + (size_t)(b * AG + row) * CH + h * HD + c0;
#pragma unroll
        for (int i = 0; i < 32; i += 2) {
            float2 v = (row < AG) ? *(const float2*)(src + i) : make_float2(0.f, 0.f);
            v.x *= 0.125f; v.y *= 0.125f;
            __nv_bfloat162 hi, lo;
            split2(v.x, hi.x, lo.x);
            split2(v.y, hi.y, lo.y);
            *(__nv_bfloat162*)&sB0[row][c0 + i] = hi;
            *(__nv_bfloat162*)&sB1[row][c0 + i] = lo;
        }
    }

    float acc[2][8][4];
#pragma unroll
    for (int mf = 0; mf < 2; mf++)
#pragma unroll
        for (int j = 0; j < 8; j++)
#pragma unroll
            for (int e = 0; e < 4; e++) acc[mf][j][e] = 0.f;

    for (int term = 0; term < 3; term++) {
        if (term != 1) {
            __syncthreads();
            int row = tid;
            int m = m0 + row;
            const float* src = g_q + ((size_t)b * NTOK + m) * CH + h * HD;
#pragma unroll
            for (int i = 0; i < 64; i += 2) {
                float2 v = (m < NTOK) ? *(const float2*)(src + i) : make_float2(0.f, 0.f);
                __nv_bfloat162 hi;
                hi.x = __float2bfloat16(v.x);
                hi.y = __float2bfloat16(v.y);
                if (term == 0) *(__nv_bfloat162*)&sQ[row][i] = hi;
                else {
                    __nv_bfloat162 lo;
                    lo.x = __float2bfloat16(v.x - __bfloat162float(hi.x));
                    lo.y = __float2bfloat16(v.y - __bfloat162float(hi.y));
                    *(__nv_bfloat162*)&sQ[row][i] = lo;
                }
            }
        }
        __syncthreads();
        __nv_bfloat16 (*Bs)[72] = (term == 1) ? sB1 : sB0;
#pragma unroll
        for (int kt = 0; kt < 4; kt++) {
            uint32_t af[2][4];
#pragma unroll
            for (int mf = 0; mf < 2; mf++)
                ldsm4(af[mf][0], af[mf][1], af[mf][2], af[mf][3],
                      smem_u32(&sQ[warp * 32 + mf * 16 + (lane & 15)][kt * 16 + ((lane >> 4) << 3)]));
#pragma unroll
            for (int p = 0; p < 4; p++) {
                uint32_t br[4];
                ldsm4(br[0], br[1], br[2], br[3],
                      smem_u32(&Bs[p * 16 + (lane & 7) + ((lane >> 4) << 3)][kt * 16 + (((lane >> 3) & 1) << 3)]));
#pragma unroll
                for (int mf = 0; mf < 2; mf++) {
                    mma16816(acc[mf][p * 2],     af[mf], br[0], br[1]);
                    mma16816(acc[mf][p * 2 + 1], af[mf], br[2], br[3]);
                }
            }
        }
    }
    __syncthreads();

    {
        int row = tid >> 1, c0 = (tid & 1) * 32;
        const float* src = g_agentv + ((size_t)(b * NH + h) * AG + row) * HD + c0;
#pragma unroll
        for (int i = 0; i < 32; i += 2) {
            float2 v = (row < AG) ? *(const float2*)(src + i) : make_float2(0.f, 0.f);
            __nv_bfloat162 hi, lo;
            split2(v.x, hi.x, lo.x);
            split2(v.y, hi.y, lo.y);
            *(__nv_bfloat162*)&sB0[row][c0 + i] = hi;
            *(__nv_bfloat162*)&sB1[row][c0 + i] = lo;
        }
    }

    float inv[2][2];
#pragma unroll
    for (int mf = 0; mf < 2; mf++) {
#pragma unroll
        for (int rh = 0; rh < 2; rh++) {
            int m = m0 + warp * 32 + mf * 16 + (lane >> 2) + rh * 8;
            const float* b2 = g_bias2 + ((size_t)h * NTOK + (m < NTOK ? m : 0)) * AG;
            float mx = -1e30f;
#pragma unroll
            for (int j = 0; j < 8; j++)
#pragma unroll
                for (int e = 0; e < 2; e++) {
                    int a = j * 8 + (lane & 3) * 2 + e;
                    float v;
                    if (a < AG) v = acc[mf][j][rh * 2 + e] + ((m < NTOK) ? b2[a] : 0.f);
                    else v = -1e30f;
                    acc[mf][j][rh * 2 + e] = v;
                    mx = fmaxf(mx, v);
                }
            mx = fmaxf(mx, __shfl_xor_sync(0xffffffffu, mx, 1));
            mx = fmaxf(mx, __shfl_xor_sync(0xffffffffu, mx, 2));
            float s = 0.f;
#pragma unroll
            for (int j = 0; j < 8; j++)
#pragma unroll
                for (int e = 0; e < 2; e++) {
                    float ev = __expf(acc[mf][j][rh * 2 + e] - mx);
                    acc[mf][j][rh * 2 + e] = ev;
                    s += ev;
                }
            s += __shfl_xor_sync(0xffffffffu, s, 1);
            s += __shfl_xor_sync(0xffffffffu, s, 2);
            inv[mf][rh] = 1.0f / s;
        }
    }
    __syncthreads();

    float o[2][8][4];
#pragma unroll
    for (int mf = 0; mf < 2; mf++)
#pragma unroll
        for (int j = 0; j < 8; j++)
#pragma unroll
            for (int e = 0; e < 4; e++) o[mf][j][e] = 0.f;

#pragma unroll
    for (int kt = 0; kt < 4; kt++) {
        uint32_t ah_[2][4], al_[2][4];
#pragma unroll
        for (int mf = 0; mf < 2; mf++)
#pragma unroll
            for (int q = 0; q < 2; q++) {
                int j = kt * 2 + q;
#pragma unroll
                for (int rh = 0; rh < 2; rh++) {
                    float v0 = acc[mf][j][rh * 2 + 0] * inv[mf][rh];
                    float v1 = acc[mf][j][rh * 2 + 1] * inv[mf][rh];
                    __nv_bfloat16 h0, l0, h1, l1;
                    split2(v0, h0, l0);
                    split2(v1, h1, l1);
                    ah_[mf][q * 2 + rh] = pack_bf2(h0, h1);
                    al_[mf][q * 2 + rh] = pack_bf2(l0, l1);
                }
            }
#pragma unroll
        for (int dp = 0; dp < 4; dp++) {
            uint32_t bh_[4], bl_[4];
            uint32_t brow = kt * 16 + (lane & 15);
            uint32_t bcol = dp * 16 + ((lane >> 4) << 3);
            ldsm4t(bh_[0], bh_[1], bh_[2], bh_[3], smem_u32(&sB0[brow][bcol]));
            ldsm4t(bl_[0], bl_[1], bl_[2], bl_[3], smem_u32(&sB1[brow][bcol]));
#pragma unroll
            for (int mf = 0; mf < 2; mf++) {
                mma16816(o[mf][dp * 2], ah_[mf], bh_[0], bh_[1]);
                mma16816(o[mf][dp * 2], ah_[mf], bl_[0], bl_[1]);
                mma16816(o[mf][dp * 2], al_[mf], bh_[0], bh_[1]);
                mma16816(o[mf][dp * 2 + 1], ah_[mf], bh_[2], bh_[3]);
                mma16816(o[mf][dp * 2 + 1], ah_[mf], bl_[2], bl_[3]);
                mma16816(o[mf][dp * 2 + 1], al_[mf], bh_[2], bh_[3]);
            }
        }
    }

#pragma unroll
    for (int mf = 0; mf < 2; mf++) {
#pragma unroll
        for (int j = 0; j < 8; j++) {
            int m = m0 + warp * 32 + mf * 16 + (lane >> 2);
            int d = j * 8 + (lane & 3) * 2;
            float* dst = g_pre + ((size_t)b * NTOK + m) * CH + h * HD + d;
            if (m < NTOK)
                *(float2*)dst = make_float2(o[mf][j][0], o[mf][j][1]);
            if (m + 8 < NTOK)
                *(float2*)(dst + 8 * CH) = make_float2(o[mf][j][2], o[mf][j][3]);
        }
    }
}

// ---------------- launch ------------------------------------------------------
extern "C" void kernel_launch(void* const* d_in, const int* in_sizes, int n_in,
                              void* d_out, int out_size) {
    int off = (in_sizes[1] == 1) ? 3 : 1;
    const float* x      = (const float*)d_in[0];
    const float* q_w    = (const float*)d_in[off + 0];
    const float* kv_w   = (const float*)d_in[off + 1];
    const float* proj_w = (const float*)d_in[off + 2];
    const float* proj_b = (const float*)d_in[off + 3];
    const float* dwc_w  = (const float*)d_in[off + 4];
    const float* dwc_b  = (const float*)d_in[off + 5];
    const float* an_b   = (const float*)d_in[off + 6];
    const float* na_b   = (const float*)d_in[off + 7];
    const float* ah_b   = (const float*)d_in[off + 8];
    const float* aw_b   = (const float*)d_in[off + 9];
    const float* ha_b   = (const float*)d_in[off + 10];
    const float* wa_b   = (const float*)d_in[off + 11];
    float* out = (float*)d_out;

    cudaFuncSetAttribute(gemm_split, cudaFuncAttributeMaxDynamicSharedMemorySize, GS_DYN);
    cudaFuncSetAttribute(agent_fused, cudaFuncAttributeMaxDynamicSharedMemorySize, AF_DYN);

    make_bias1<<<dim3(AG, NH), 256>>>(an_b, ah_b, aw_b);
    make_bias2<<<dim3(NTOK, NH), 64>>>(na_b, ha_b, wa_b);

    pack_a<<<MROWS, 256>>>(x);
    pack_b<<<3 * CH, 256>>>(q_w, kv_w, 1);
    gemm_split<<<dim3(1536 / 128, MROWS / 128), 256, GS_DYN>>>(0, nullptr, nullptr);

    agent_pool<<<dim3(AG, BQ), CH>>>();
    agent_fused<<<dim3(NH, BQ, KS), 128, AF_DYN>>>();
    agent_combine<<<BQ * NH, 64>>>();
    qside_mma<<<dim3(25, NH, BQ), 128>>>();

    pack_a_dwc<<<MROWS, 256>>>(dwc_w, dwc_b);
    pack_b<<<CH, 256>>>(proj_w, nullptr, 0);
    gemm_split<<<dim3(CH / 128, MROWS / 128), 256, GS_DYN>>>(1, proj_b, out);
}

// round 14
// speedup vs baseline: 1.4192x; 1.4192x over previous
#include <cuda_runtime.h>
#include <cuda_bf16.h>
#include <math.h>
#include <stdint.h>

#define BQ 16
#define CH 512
#define HH 56
#define WWD 56
#define NTOK 3136          // 56*56
#define NH 8
#define HD 64
#define AG 49
#define MROWS (BQ*NTOK)    // 50176
#define K2 1024            // packed K: [hi(512) | lo(512)]
#define NKIT 16            // 512 / 32 k-chunks
#define KS 4               // agent flash k-splits

// ---------------- scratch ----------------------------------------------------
__device__ float g_q[(size_t)MROWS * CH];
__device__ float g_k[(size_t)MROWS * CH];
__device__ float g_v[(size_t)MROWS * CH];
__device__ float g_pre[(size_t)MROWS * CH];
__device__ float g_agent[BQ * AG * CH];
__device__ float g_bias1[NH * AG * NTOK];          // [h][a][n]
__device__ float g_bias2[(size_t)NH * NTOK * AG];  // [h][n][a]
__device__ float g_agentv[BQ * NH * AG * HD];
__device__ float g_po[KS][BQ * NH][AG][HD];        // partial flash O
__device__ float g_pml[KS][BQ * NH][AG][2];        // partial flash m,l
__device__ __nv_bfloat16 g_abf[(size_t)MROWS * K2];
__device__ __nv_bfloat16 g_bbf[(size_t)3 * CH * K2];

// ---------------- helpers ----------------------------------------------------
__device__ __forceinline__ void split2(float v, __nv_bfloat16& hi, __nv_bfloat16& lo) {
    hi = __float2bfloat16(v);
    lo = __float2bfloat16(v - __bfloat162float(hi));
}
__device__ __forceinline__ uint32_t pack_bf2(__nv_bfloat16 a, __nv_bfloat16 b) {
    return ((uint32_t)__bfloat16_as_ushort(b) << 16) | (uint32_t)__bfloat16_as_ushort(a);
}
__device__ __forceinline__ uint32_t smem_u32(const void* p) {
    return (uint32_t)__cvta_generic_to_shared(p);
}
__device__ __forceinline__ void ldsm4(uint32_t& r0, uint32_t& r1, uint32_t& r2, uint32_t& r3, uint32_t addr) {
    asm volatile("ldmatrix.sync.aligned.m8n8.x4.shared.b16 {%0,%1,%2,%3}, [%4];"
                 : "=r"(r0), "=r"(r1), "=r"(r2), "=r"(r3) : "r"(addr));
}
__device__ __forceinline__ void ldsm4t(uint32_t& r0, uint32_t& r1, uint32_t& r2, uint32_t& r3, uint32_t addr) {
    asm volatile("ldmatrix.sync.aligned.m8n8.x4.trans.shared.b16 {%0,%1,%2,%3}, [%4];"
                 : "=r"(r0), "=r"(r1), "=r"(r2), "=r"(r3) : "r"(addr));
}
__device__ __forceinline__ void mma16816(float* c, const uint32_t* a, uint32_t b0, uint32_t b1) {
    asm volatile("mma.sync.aligned.m16n8k16.row.col.f32.bf16.bf16.f32 "
                 "{%0,%1,%2,%3}, {%4,%5,%6,%7}, {%8,%9}, {%0,%1,%2,%3};"
                 : "+f"(c[0]), "+f"(c[1]), "+f"(c[2]), "+f"(c[3])
                 : "r"(a[0]), "r"(a[1]), "r"(a[2]), "r"(a[3]), "r"(b0), "r"(b1));
}
__device__ __forceinline__ void cp16(uint32_t sp, const void* gp) {
    asm volatile("cp.async.cg.shared.global [%0], [%1], 16;\n" :: "r"(sp), "l"(gp));
}

// ---------------- pack kernels -----------------------------------------------
__global__ void pack_a(const float* __restrict__ src) {
    int row = blockIdx.x;
    int kp = threadIdx.x * 2;
    float2 v = *(const float2*)&src[(size_t)row * CH + kp];
    __nv_bfloat162 h2, l2;
    split2(v.x, h2.x, l2.x);
    split2(v.y, h2.y, l2.y);
    __nv_bfloat16* dst = g_abf + (size_t)row * K2;
    *(__nv_bfloat162*)&dst[kp]       = h2;
    *(__nv_bfloat162*)&dst[kp + 512] = l2;
}
__global__ void pack_a_dwc(const float* __restrict__ w, const float* __restrict__ dbias) {
    int row = blockIdx.x;           // b*3136 + n
    int c = threadIdx.x * 2;
    int n = row % NTOK, b = row / NTOK;
    int y = n / WWD, x = n % WWD;
    float a0 = dbias[c], a1 = dbias[c + 1];
#pragma unroll
    for (int ky = 0; ky < 3; ky++) {
        int yy = y + ky - 1;
        if (yy < 0 || yy >= HH) continue;
#pragma unroll
        for (int kx = 0; kx < 3; kx++) {
            int xx = x + kx - 1;
            if (xx < 0 || xx >= WWD) continue;
            float2 vv = *(const float2*)&g_v[((size_t)b * NTOK + yy * WWD + xx) * CH + c];
            int ki = ky * 3 + kx;
            a0 = fmaf(vv.x, w[c * 9 + ki], a0);
            a1 = fmaf(vv.y, w[(c + 1) * 9 + ki], a1);
        }
    }
    float2 p = *(const float2*)&g_pre[(size_t)row * CH + c];
    float v0 = p.x + a0, v1 = p.y + a1;
    __nv_bfloat162 h2, l2;
    split2(v0, h2.x, l2.x);
    split2(v1, h2.y, l2.y);
    __nv_bfloat16* dst = g_abf + (size_t)row * K2;
    *(__nv_bfloat162*)&dst[c]       = h2;
    *(__nv_bfloat162*)&dst[c + 512] = l2;
}
__global__ void pack_b(const float* __restrict__ w0, const float* __restrict__ w1, int qkv) {
    int row = blockIdx.x;
    int kp = threadIdx.x * 2;
    const float* src;
    if (qkv) src = (row < CH) ? (w0 + (size_t)row * CH) : (w1 + (size_t)(row - CH) * CH);
    else     src = w0 + (size_t)row * CH;
    float2 v = *(const float2*)&src[kp];
    __nv_bfloat162 h2, l2;
    split2(v.x, h2.x, l2.x);
    split2(v.y, h2.y, l2.y);
    __nv_bfloat16* dst = g_bbf + (size_t)row * K2;
    *(__nv_bfloat162*)&dst[kp]       = h2;
    *(__nv_bfloat162*)&dst[kp + 512] = l2;
}

// ---------------- split bf16 GEMM: C = Ah*Bh + Ah*Bl + Al*Bh ------------------
// 128x128 tile, 256 thr, 32-wide k-chunks, 3-stage cp.async (R10-proven form).
#define OPS (128 * 40)
#define GS_DYN (3 * 4 * OPS * 2)
__global__ void __launch_bounds__(256) gemm_split(int mode, const float* __restrict__ bias,
                                                  float* __restrict__ out) {
    extern __shared__ __nv_bfloat16 smg[];
    const int tid = threadIdx.x;
    const int lane = tid & 31;
    const int warp = tid >> 5;
    const int wm = (warp & 1) * 64;
    const int wn = (warp >> 1) * 32;
    const int m0 = blockIdx.y * 128;
    const int n0 = blockIdx.x * 128;
    const uint32_t sb = smem_u32(smg);

    float acc[4][4][4];
#pragma unroll
    for (int i = 0; i < 4; i++)
#pragma unroll
        for (int j = 0; j < 4; j++)
#pragma unroll
            for (int l = 0; l < 4; l++) acc[i][j][l] = 0.f;

#define ISSUE(st, ch)                                                                     \
    {                                                                                     \
        uint32_t bse = (uint32_t)(st) * (4 * OPS);                                        \
        _Pragma("unroll")                                                                 \
        for (int it = 0; it < 2; it++) {                                                  \
            int id = it * 256 + tid;                                                      \
            int row = id >> 2;                                                            \
            int c8 = (id & 3) * 8;                                                        \
            int k = (ch) * 32 + c8;                                                       \
            cp16(sb + (bse + row * 40 + c8) * 2,           g_abf + (size_t)(m0 + row) * K2 + k);        \
            cp16(sb + (bse + OPS + row * 40 + c8) * 2,     g_abf + (size_t)(m0 + row) * K2 + 512 + k);  \
            cp16(sb + (bse + 2 * OPS + row * 40 + c8) * 2, g_bbf + (size_t)(n0 + row) * K2 + k);        \
            cp16(sb + (bse + 3 * OPS + row * 40 + c8) * 2, g_bbf + (size_t)(n0 + row) * K2 + 512 + k);  \
        }                                                                                 \
        asm volatile("cp.async.commit_group;\n");                                         \
    }

    ISSUE(0, 0);
    ISSUE(1, 1);
    for (int c = 0; c < NKIT; c++) {
        if (c + 1 < NKIT) asm volatile("cp.async.wait_group 1;\n");
        else              asm volatile("cp.async.wait_group 0;\n");
        __syncthreads();
        if (c + 2 < NKIT) ISSUE((c + 2) % 3, c + 2);
        uint32_t bse = (uint32_t)(c % 3) * (4 * OPS);
#pragma unroll
        for (int ks = 0; ks < 32; ks += 16) {
            uint32_t a_h[4][4], a_l[4][4];
#pragma unroll
            for (int fm = 0; fm < 4; fm++) {
                uint32_t ro = (uint32_t)((wm + fm * 16 + (lane & 15)) * 40 + ks + ((lane >> 4) << 3));
                ldsm4(a_h[fm][0], a_h[fm][1], a_h[fm][2], a_h[fm][3], sb + (bse + ro) * 2);
                ldsm4(a_l[fm][0], a_l[fm][1], a_l[fm][2], a_l[fm][3], sb + (bse + OPS + ro) * 2);
            }
#pragma unroll
            for (int fn = 0; fn < 2; fn++) {
                uint32_t ro = (uint32_t)((wn + fn * 16 + (lane & 7) + ((lane >> 4) << 3)) * 40
                                         + ks + (((lane >> 3) & 1) << 3));
                uint32_t bh[4], bl[4];
                ldsm4(bh[0], bh[1], bh[2], bh[3], sb + (bse + 2 * OPS + ro) * 2);
                ldsm4(bl[0], bl[1], bl[2], bl[3], sb + (bse + 3 * OPS + ro) * 2);
#pragma unroll
                for (int q = 0; q < 2; q++) {
                    int nc = fn * 2 + q;
                    uint32_t b0h = bh[q ? 2 : 0], b1h = bh[q ? 3 : 1];
                    uint32_t b0l = bl[q ? 2 : 0], b1l = bl[q ? 3 : 1];
#pragma unroll
                    for (int fm = 0; fm < 4; fm++) {
                        mma16816(acc[fm][nc], a_h[fm], b0h, b1h);
                        mma16816(acc[fm][nc], a_h[fm], b0l, b1l);
                        mma16816(acc[fm][nc], a_l[fm], b0h, b1h);
                    }
                }
            }
        }
    }

    const int r0 = lane >> 2;
    const int cp = (lane & 3) * 2;
#pragma unroll
    for (int fm = 0; fm < 4; fm++) {
#pragma unroll
        for (int nc = 0; nc < 4; nc++) {
            int m = m0 + wm + fm * 16 + r0;
            int n = n0 + wn + nc * 8 + cp;
            if (mode == 0) {
                float* dst = (n < CH) ? g_q : ((n < 2 * CH) ? g_k : g_v);
                int nn = n & (CH - 1);
                *(float2*)&dst[(size_t)m * CH + nn] = make_float2(acc[fm][nc][0], acc[fm][nc][1]);
                *(float2*)&dst[(size_t)(m + 8) * CH + nn] = make_float2(acc[fm][nc][2], acc[fm][nc][3]);
            } else {
                float2 bb = *(const float2*)&bias[n];
                *(float2*)&out[(size_t)m * CH + n] =
                    make_float2(acc[fm][nc][0] + bb.x, acc[fm][nc][1] + bb.y);
                *(float2*)&out[(size_t)(m + 8) * CH + n] =
                    make_float2(acc[fm][nc][2] + bb.x, acc[fm][nc][3] + bb.y);
            }
        }
    }
#undef ISSUE
}

// ---------------- bias precompute --------------------------------------------
__device__ __forceinline__ float resize77(const float* __restrict__ img, int y, int x) {
    float sy = (y + 0.5f) * 0.125f - 0.5f;
    float sx = (x + 0.5f) * 0.125f - 0.5f;
    int y0 = (int)floorf(sy); float fy = sy - (float)y0;
    int x0 = (int)floorf(sx); float fx = sx - (float)x0;
    int y1 = y0 + 1, x1 = x0 + 1;
    float wy0 = 1.f - fy, wy1 = fy, wx0 = 1.f - fx, wx1 = fx;
    if (y0 < 0)  { y0 = 0; wy0 = 0.f; wy1 = 1.f; }
    if (y1 > 6)  { y1 = 6; wy0 = 1.f; wy1 = 0.f; }
    if (x0 < 0)  { x0 = 0; wx0 = 0.f; wx1 = 1.f; }
    if (x1 > 6)  { x1 = 6; wx0 = 1.f; wx1 = 0.f; }
    return wy0 * (wx0 * img[y0 * 7 + x0] + wx1 * img[y0 * 7 + x1]) +
           wy1 * (wx0 * img[y1 * 7 + x0] + wx1 * img[y1 * 7 + x1]);
}
__global__ void make_bias1(const float* __restrict__ an, const float* __restrict__ ahb,
                           const float* __restrict__ awb) {
    int h = blockIdx.y, a = blockIdx.x;
    const float* img = an + (h * AG + a) * 49;
    for (int n = threadIdx.x; n < NTOK; n += blockDim.x) {
        int y = n / WWD, x = n % WWD;
        g_bias1[(h * AG + a) * NTOK + n] =
            resize77(img, y, x) + ahb[(h * AG + a) * HH + y] + awb[(h * AG + a) * WWD + x];
    }
}
__global__ void make_bias2(const float* __restrict__ na, const float* __restrict__ hab,
                           const float* __restrict__ wab) {
    int h = blockIdx.y, n = blockIdx.x;
    int y = n / WWD, x = n % WWD;
    int a = threadIdx.x;
    if (a < AG) {
        g_bias2[((size_t)h * NTOK + n) * AG + a] =
            resize77(na + (h * AG + a) * 49, y, x) + hab[(h * HH + y) * AG + a] + wab[(h * WWD + x) * AG + a];
    }
}

// ---------------- agent pooling ----------------------------------------------
__global__ void agent_pool() {
    int a = blockIdx.x, b = blockIdx.y, c = threadIdx.x;
    int ph = a / 7, pw = a % 7;
    const float* base = g_q + (size_t)b * NTOK * CH;
    float s = 0.f;
#pragma unroll
    for (int ih = 0; ih < 8; ih++)
#pragma unroll
        for (int iw = 0; iw < 8; iw++)
            s += base[(size_t)((ph * 8 + ih) * WWD + pw * 8 + iw) * CH + c];
    g_agent[(b * AG + a) * CH + c] = s * (1.0f / 64.0f);
}

// ---------------- fused agent-side flash attention (k-split) ------------------
#define AF_DYN ((64 + 64 + 128 + 128 + 128 + 128) * 72 * 2)
__global__ void __launch_bounds__(128) agent_fused() {
    extern __shared__ __nv_bfloat16 smf[];
    __nv_bfloat16 (*sA0)[72] = (__nv_bfloat16(*)[72])smf;
    __nv_bfloat16 (*sA1)[72] = sA0 + 64;
    __nv_bfloat16 (*sK0)[72] = sA1 + 64;
    __nv_bfloat16 (*sK1)[72] = sK0 + 128;
    __nv_bfloat16 (*sV0)[72] = sK1 + 128;
    __nv_bfloat16 (*sV1)[72] = sV0 + 128;
    int h = blockIdx.x, b = blockIdx.y, z = blockIdx.z;
    int bh = b * NH + h;
    int tid = threadIdx.x, lane = tid & 31, warp = tid >> 5;
    int t0 = (z * 25) / KS, t1 = ((z + 1) * 25) / KS;

    {   // ah*scale split (rows >= 49 zero)
        int row = tid >> 1, c0 = (tid & 1) * 32;
        const float* src = g_agent + (size_t)(b * AG + row) * CH + h * HD + c0;
#pragma unroll
        for (int i = 0; i < 32; i += 2) {
            float2 v = (row < AG) ? *(const float2*)(src + i) : make_float2(0.f, 0.f);
            v.x *= 0.125f; v.y *= 0.125f;
            __nv_bfloat162 hi, lo;
            split2(v.x, hi.x, lo.x);
            split2(v.y, hi.y, lo.y);
            *(__nv_bfloat162*)&sA0[row][c0 + i] = hi;
            *(__nv_bfloat162*)&sA1[row][c0 + i] = lo;
        }
    }

    float m_run[2] = {-1e30f, -1e30f};
    float l_run[2] = {0.f, 0.f};
    float o[8][4];
#pragma unroll
    for (int j = 0; j < 8; j++)
#pragma unroll
        for (int e = 0; e < 4; e++) o[j][e] = 0.f;

    for (int t = t0; t < t1; t++) {
        int n0 = t * 128;
        __syncthreads();
        {
            int n = n0 + tid;
            bool valid = (n < NTOK);
            const float* ksrc = g_k + ((size_t)b * NTOK + (valid ? n : 0)) * CH + h * HD;
            const float* vsrc = g_v + ((size_t)b * NTOK + (valid ? n : 0)) * CH + h * HD;
#pragma unroll
            for (int i = 0; i < 64; i += 2) {
                float2 kv = valid ? *(const float2*)(ksrc + i) : make_float2(0.f, 0.f);
                float2 vv = valid ? *(const float2*)(vsrc + i) : make_float2(0.f, 0.f);
                __nv_bfloat162 khi, klo, vhi, vlo;
                split2(kv.x, khi.x, klo.x); split2(kv.y, khi.y, klo.y);
                split2(vv.x, vhi.x, vlo.x); split2(vv.y, vhi.y, vlo.y);
                *(__nv_bfloat162*)&sK0[tid][i] = khi;
                *(__nv_bfloat162*)&sK1[tid][i] = klo;
                *(__nv_bfloat162*)&sV0[tid][i] = vhi;
                *(__nv_bfloat162*)&sV1[tid][i] = vlo;
            }
        }
        __syncthreads();

        float s[16][4];
#pragma unroll
        for (int j = 0; j < 16; j++)
#pragma unroll
            for (int e = 0; e < 4; e++) s[j][e] = 0.f;
#pragma unroll
        for (int kt = 0; kt < 4; kt++) {
            uint32_t a0[4], a1[4];
            uint32_t aro = smem_u32(&sA0[warp * 16 + (lane & 15)][kt * 16 + ((lane >> 4) << 3)]);
            uint32_t aro1 = smem_u32(&sA1[warp * 16 + (lane & 15)][kt * 16 + ((lane >> 4) << 3)]);
            ldsm4(a0[0], a0[1], a0[2], a0[3], aro);
            ldsm4(a1[0], a1[1], a1[2], a1[3], aro1);
#pragma unroll
            for (int p = 0; p < 8; p++) {
                uint32_t bro = (uint32_t)((p * 16 + (lane & 7) + ((lane >> 4) << 3)) * 72
                                          + kt * 16 + (((lane >> 3) & 1) << 3));
                uint32_t bh[4], bl[4];
                ldsm4(bh[0], bh[1], bh[2], bh[3], smem_u32(sK0) + bro * 2);
                ldsm4(bl[0], bl[1], bl[2], bl[3], smem_u32(sK1) + bro * 2);
                mma16816(s[p * 2],     a0, bh[0], bh[1]);
                mma16816(s[p * 2],     a0, bl[0], bl[1]);
                mma16816(s[p * 2],     a1, bh[0], bh[1]);
                mma16816(s[p * 2 + 1], a0, bh[2], bh[3]);
                mma16816(s[p * 2 + 1], a0, bl[2], bl[3]);
                mma16816(s[p * 2 + 1], a1, bh[2], bh[3]);
            }
        }

#pragma unroll
        for (int rh = 0; rh < 2; rh++) {
            int a = warp * 16 + (lane >> 2) + rh * 8;
            bool av = (a < AG);
            const float* b1p = g_bias1 + (size_t)(h * AG + (av ? a : 0)) * NTOK;
            float mx = m_run[rh];
#pragma unroll
            for (int j = 0; j < 16; j++) {
                int n = n0 + j * 8 + (lane & 3) * 2;
                bool nv = av && (n < NTOK);
                float2 bb = nv ? *(const float2*)(b1p + n) : make_float2(0.f, 0.f);
                float v0 = nv ? (s[j][rh * 2] + bb.x) : -1e30f;
                float v1 = nv ? (s[j][rh * 2 + 1] + bb.y) : -1e30f;
                s[j][rh * 2] = v0;
                s[j][rh * 2 + 1] = v1;
                mx = fmaxf(mx, fmaxf(v0, v1));
            }
            mx = fmaxf(mx, __shfl_xor_sync(0xffffffffu, mx, 1));
            mx = fmaxf(mx, __shfl_xor_sync(0xffffffffu, mx, 2));
            float scale = __expf(m_run[rh] - mx);
            float sum = 0.f;
#pragma unroll
            for (int j = 0; j < 16; j++) {
                float e0 = __expf(s[j][rh * 2] - mx);
                float e1 = __expf(s[j][rh * 2 + 1] - mx);
                s[j][rh * 2] = e0;
                s[j][rh * 2 + 1] = e1;
                sum += e0 + e1;
            }
            sum += __shfl_xor_sync(0xffffffffu, sum, 1);
            sum += __shfl_xor_sync(0xffffffffu, sum, 2);
            l_run[rh] = l_run[rh] * scale + sum;
            m_run[rh] = mx;
#pragma unroll
            for (int j = 0; j < 8; j++) {
                o[j][rh * 2] *= scale;
                o[j][rh * 2 + 1] *= scale;
            }
        }

#pragma unroll
        for (int kt = 0; kt < 8; kt++) {
            uint32_t ah4[4], al4[4];
#pragma unroll
            for (int q = 0; q < 2; q++) {
                int j = kt * 2 + q;
#pragma unroll
                for (int rh = 0; rh < 2; rh++) {
                    __nv_bfloat16 h0, l0, h1, l1;
                    split2(s[j][rh * 2], h0, l0);
                    split2(s[j][rh * 2 + 1], h1, l1);
                    ah4[q * 2 + rh] = pack_bf2(h0, h1);
                    al4[q * 2 + rh] = pack_bf2(l0, l1);
                }
            }
#pragma unroll
            for (int dp = 0; dp < 4; dp++) {
                uint32_t bro = (uint32_t)((kt * 16 + (lane & 15)) * 72 + dp * 16 + ((lane >> 4) << 3));
                uint32_t vh[4], vl[4];
                ldsm4t(vh[0], vh[1], vh[2], vh[3], smem_u32(sV0) + bro * 2);
                ldsm4t(vl[0], vl[1], vl[2], vl[3], smem_u32(sV1) + bro * 2);
                mma16816(o[dp * 2],     ah4, vh[0], vh[1]);
                mma16816(o[dp * 2],     ah4, vl[0], vl[1]);
                mma16816(o[dp * 2],     al4, vh[0], vh[1]);
                mma16816(o[dp * 2 + 1], ah4, vh[2], vh[3]);
                mma16816(o[dp * 2 + 1], ah4, vl[2], vl[3]);
                mma16816(o[dp * 2 + 1], al4, vh[2], vh[3]);
            }
        }
    }

#pragma unroll
    for (int rh = 0; rh < 2; rh++) {
        int a = warp * 16 + (lane >> 2) + rh * 8;
        if (a < AG) {
            float* dst = g_po[z][bh][a];
#pragma unroll
            for (int j = 0; j < 8; j++) {
                int d = j * 8 + (lane & 3) * 2;
                *(float2*)(dst + d) = make_float2(o[j][rh * 2], o[j][rh * 2 + 1]);
            }
            if ((lane & 3) == 0) {
                g_pml[z][bh][a][0] = m_run[rh];
                g_pml[z][bh][a][1] = l_run[rh];
            }
        }
    }
}

// combine partial flash results across KS splits
__global__ void agent_combine() {
    int bh = blockIdx.x;
    int d = threadIdx.x;   // 64
    for (int a = 0; a < AG; a++) {
        float m = -1e30f;
#pragma unroll
        for (int z = 0; z < KS; z++) m = fmaxf(m, g_pml[z][bh][a][0]);
        float l = 0.f, o = 0.f;
#pragma unroll
        for (int z = 0; z < KS; z++) {
            float w = __expf(g_pml[z][bh][a][0] - m);
            l = fmaf(g_pml[z][bh][a][1], w, l);
            o = fmaf(g_po[z][bh][a][d], w, o);
        }
        g_agentv[((size_t)bh * AG + a) * HD + d] = o / l;
    }
}

// ---------------- q-side fused flash (mma.sync) -------------------------------
__global__ void __launch_bounds__(128) qside_mma() {
    __shared__ __nv_bfloat16 sQ[128][72];
    __shared__ __nv_bfloat16 sB0[64][72];
    __shared__ __nv_bfloat16 sB1[64][72];
    int b = blockIdx.z, h = blockIdx.y, m0 = blockIdx.x * 128;
    int tid = threadIdx.x, lane = tid & 31, warp = tid >> 5;

    {
        int row = tid >> 1, c0 = (tid & 1) * 32;
        const float* src = g_agent + (size_t)(b * AG + row) * CH + h * HD + c0;
#pragma unroll
        for (int i = 0; i < 32; i += 2) {
            float2 v = (row < AG) ? *(const float2*)(src + i) : make_float2(0.f, 0.f);
            v.x *= 0.125f; v.y *= 0.125f;
            __nv_bfloat162 hi, lo;
            split2(v.x, hi.x, lo.x);
            split2(v.y, hi.y, lo.y);
            *(__nv_bfloat162*)&sB0[row][c0 + i] = hi;
            *(__nv_bfloat162*)&sB1[row][c0 + i] = lo;
        }
    }

    float acc[2][8][4];
#pragma unroll
    for (int mf = 0; mf < 2; mf++)
#pragma unroll
        for (int j = 0; j < 8; j++)
#pragma unroll
            for (int e = 0; e < 4; e++) acc[mf][j][e] = 0.f;

    for (int term = 0; term < 3; term++) {
        if (term != 1) {
            __syncthreads();
            int row = tid;
            int m = m0 + row;
            const float* src = g_q + ((size_t)b * NTOK + m) * CH + h * HD;
#pragma unroll
            for (int i = 0; i < 64; i += 2) {
                float2 v = (m < NTOK) ? *(const float2*)(src + i) : make_float2(0.f, 0.f);
                __nv_bfloat162 hi;
                hi.x = __float2bfloat16(v.x);
                hi.y = __float2bfloat16(v.y);
                if (term == 0) *(__nv_bfloat162*)&sQ[row][i] = hi;
                else {
                    __nv_bfloat162 lo;
                    lo.x = __float2bfloat16(v.x - __bfloat162float(hi.x));
                    lo.y = __float2bfloat16(v.y - __bfloat162float(hi.y));
                    *(__nv_bfloat162*)&sQ[row][i] = lo;
                }
            }
        }
        __syncthreads();
        __nv_bfloat16 (*Bs)[72] = (term == 1) ? sB1 : sB0;
#pragma unroll
        for (int kt = 0; kt < 4; kt++) {
            uint32_t af[2][4];
#pragma unroll
            for (int mf = 0; mf < 2; mf++)
                ldsm4(af[mf][0], af[mf][1], af[mf][2], af[mf][3],
                      smem_u32(&sQ[warp * 32 + mf * 16 + (lane & 15)][kt * 16 + ((lane >> 4) << 3)]));
#pragma unroll
            for (int p = 0; p < 4; p++) {
                uint32_t br[4];
                ldsm4(br[0], br[1], br[2], br[3],
                      smem_u32(&Bs[p * 16 + (lane & 7) + ((lane >> 4) << 3)][kt * 16 + (((lane >> 3) & 1) << 3)]));
#pragma unroll
                for (int mf = 0; mf < 2; mf++) {
                    mma16816(acc[mf][p * 2],     af[mf], br[0], br[1]);
                    mma16816(acc[mf][p * 2 + 1], af[mf], br[2], br[3]);
                }
            }
        }
    }
    __syncthreads();

    {
        int row = tid >> 1, c0 = (tid & 1) * 32;
        const float* src = g_agentv + ((size_t)(b * NH + h) * AG + row) * HD + c0;
#pragma unroll
        for (int i = 0; i < 32; i += 2) {
            float2 v = (row < AG) ? *(const float2*)(src + i) : make_float2(0.f, 0.f);
            __nv_bfloat162 hi, lo;
            split2(v.x, hi.x, lo.x);
            split2(v.y, hi.y, lo.y);
            *(__nv_bfloat162*)&sB0[row][c0 + i] = hi;
            *(__nv_bfloat162*)&sB1[row][c0 + i] = lo;
        }
    }

    float inv[2][2];
#pragma unroll
    for (int mf = 0; mf < 2; mf++) {
#pragma unroll
        for (int rh = 0; rh < 2; rh++) {
            int m = m0 + warp * 32 + mf * 16 + (lane >> 2) + rh * 8;
            const float* b2 = g_bias2 + ((size_t)h * NTOK + (m < NTOK ? m : 0)) * AG;
            float mx = -1e30f;
#pragma unroll
            for (int j = 0; j < 8; j++)
#pragma unroll
                for (int e = 0; e < 2; e++) {
                    int a = j * 8 + (lane & 3) * 2 + e;
                    float v;
                    if (a < AG) v = acc[mf][j][rh * 2 + e] + ((m < NTOK) ? b2[a] : 0.f);
                    else v = -1e30f;
                    acc[mf][j][rh * 2 + e] = v;
                    mx = fmaxf(mx, v);
                }
            mx = fmaxf(mx, __shfl_xor_sync(0xffffffffu, mx, 1));
            mx = fmaxf(mx, __shfl_xor_sync(0xffffffffu, mx, 2));
            float s = 0.f;
#pragma unroll
            for (int j = 0; j < 8; j++)
#pragma unroll
                for (int e = 0; e < 2; e++) {
                    float ev = __expf(acc[mf][j][rh * 2 + e] - mx);
                    acc[mf][j][rh * 2 + e] = ev;
                    s += ev;
                }
            s += __shfl_xor_sync(0xffffffffu, s, 1);
            s += __shfl_xor_sync(0xffffffffu, s, 2);
            inv[mf][rh] = 1.0f / s;
        }
    }
    __syncthreads();

    float o[2][8][4];
#pragma unroll
    for (int mf = 0; mf < 2; mf++)
#pragma unroll
        for (int j = 0; j < 8; j++)
#pragma unroll
            for (int e = 0; e < 4; e++) o[mf][j][e] = 0.f;

#pragma unroll
    for (int kt = 0; kt < 4; kt++) {
        uint32_t ah_[2][4], al_[2][4];
#pragma unroll
        for (int mf = 0; mf < 2; mf++)
#pragma unroll
            for (int q = 0; q < 2; q++) {
                int j = kt * 2 + q;
#pragma unroll
                for (int rh = 0; rh < 2; rh++) {
                    float v0 = acc[mf][j][rh * 2 + 0] * inv[mf][rh];
                    float v1 = acc[mf][j][rh * 2 + 1] * inv[mf][rh];
                    __nv_bfloat16 h0, l0, h1, l1;
                    split2(v0, h0, l0);
                    split2(v1, h1, l1);
                    ah_[mf][q * 2 + rh] = pack_bf2(h0, h1);
                    al_[mf][q * 2 + rh] = pack_bf2(l0, l1);
                }
            }
#pragma unroll
        for (int dp = 0; dp < 4; dp++) {
            uint32_t bh_[4], bl_[4];
            uint32_t brow = kt * 16 + (lane & 15);
            uint32_t bcol = dp * 16 + ((lane >> 4) << 3);
            ldsm4t(bh_[0], bh_[1], bh_[2], bh_[3], smem_u32(&sB0[brow][bcol]));
            ldsm4t(bl_[0], bl_[1], bl_[2], bl_[3], smem_u32(&sB1[brow][bcol]));
#pragma unroll
            for (int mf = 0; mf < 2; mf++) {
                mma16816(o[mf][dp * 2], ah_[mf], bh_[0], bh_[1]);
                mma16816(o[mf][dp * 2], ah_[mf], bl_[0], bl_[1]);
                mma16816(o[mf][dp * 2], al_[mf], bh_[0], bh_[1]);
                mma16816(o[mf][dp * 2 + 1], ah_[mf], bh_[2], bh_[3]);
                mma16816(o[mf][dp * 2 + 1], ah_[mf], bl_[2], bl_[3]);
                mma16816(o[mf][dp * 2 + 1], al_[mf], bh_[2], bh_[3]);
            }
        }
    }

#pragma unroll
    for (int mf = 0; mf < 2; mf++) {
#pragma unroll
        for (int j = 0; j < 8; j++) {
            int m = m0 + warp * 32 + mf * 16 + (lane >> 2);
            int d = j * 8 + (lane & 3) * 2;
            float* dst = g_pre + ((size_t)b * NTOK + m) * CH + h * HD + d;
            if (m < NTOK)
                *(float2*)dst = make_float2(o[mf][j][0], o[mf][j][1]);
            if (m + 8 < NTOK)
                *(float2*)(dst + 8 * CH) = make_float2(o[mf][j][2], o[mf][j][3]);
        }
    }
}

// ---------------- launch ------------------------------------------------------
extern "C" void kernel_launch(void* const* d_in, const int* in_sizes, int n_in,
                              void* d_out, int out_size) {
    int off = (in_sizes[1] == 1) ? 3 : 1;
    const float* x      = (const float*)d_in[0];
    const float* q_w    = (const float*)d_in[off + 0];
    const float* kv_w   = (const float*)d_in[off + 1];
    const float* proj_w = (const float*)d_in[off + 2];
    const float* proj_b = (const float*)d_in[off + 3];
    const float* dwc_w  = (const float*)d_in[off + 4];
    const float* dwc_b  = (const float*)d_in[off + 5];
    const float* an_b   = (const float*)d_in[off + 6];
    const float* na_b   = (const float*)d_in[off + 7];
    const float* ah_b   = (const float*)d_in[off + 8];
    const float* aw_b   = (const float*)d_in[off + 9];
    const float* ha_b   = (const float*)d_in[off + 10];
    const float* wa_b   = (const float*)d_in[off + 11];
    float* out = (float*)d_out;

    cudaFuncSetAttribute(gemm_split, cudaFuncAttributeMaxDynamicSharedMemorySize, GS_DYN);
    cudaFuncSetAttribute(agent_fused, cudaFuncAttributeMaxDynamicSharedMemorySize, AF_DYN);

    make_bias1<<<dim3(AG, NH), 256>>>(an_b, ah_b, aw_b);
    make_bias2<<<dim3(NTOK, NH), 64>>>(na_b, ha_b, wa_b);

    pack_a<<<MROWS, 256>>>(x);
    pack_b<<<3 * CH, 256>>>(q_w, kv_w, 1);
    gemm_split<<<dim3(1536 / 128, MROWS / 128), 256, GS_DYN>>>(0, nullptr, nullptr);

    agent_pool<<<dim3(AG, BQ), CH>>>();
    agent_fused<<<dim3(NH, BQ, KS), 128, AF_DYN>>>();
    agent_combine<<<BQ * NH, 64>>>();
    qside_mma<<<dim3(25, NH, BQ), 128>>>();

    pack_a_dwc<<<MROWS, 256>>>(dwc_w, dwc_b);
    pack_b<<<CH, 256>>>(proj_w, nullptr, 0);
    gemm_split<<<dim3(CH / 128, MROWS / 128), 256, GS_DYN>>>(1, proj_b, out);
}